// round 14
// baseline (speedup 1.0000x reference)
#include <cuda_runtime.h>
#include <cuda_fp16.h>
#include <math.h>
#include <stdint.h>

#define B_ 2
#define L_ 2048
#define C_ 1024
#define H_ 16
#define M_ 4096   // B_*L_

// ---------------- scratch (static device globals; no allocation) ----------------
__device__ float    g_mod6[B_ * 6 * C_];
__device__ __half   g_h[M_ * C_];          // LN outputs (half)
__device__ __half   g_qkv[M_ * 3 * C_];    // qkv (half)
__device__ __half   g_o[M_ * C_];          // attention out (half)
__device__ float    g_x[M_ * C_];          // residual stream (f32)
__device__ __half   g_g[M_ * 4 * C_];      // fc1 out (half)
__device__ __half   g_wh[12 * C_ * C_];    // transposed half weights [N][K]

// ---------------- cp.async helpers ----------------
__device__ __forceinline__ void cp16(uint32_t dst, const void* src) {
    asm volatile("cp.async.cg.shared.global [%0], [%1], 16;\n" :: "r"(dst), "l"(src));
}
#define CP_COMMIT() asm volatile("cp.async.commit_group;\n" ::: "memory")
#define CP_WAIT(n)  asm volatile("cp.async.wait_group %0;\n" :: "n"(n) : "memory")

// ---------------- mma / ldmatrix helpers ----------------
__device__ __forceinline__ void mma_f16(float* d, const uint32_t* a, const uint32_t* b) {
    asm volatile(
        "mma.sync.aligned.m16n8k16.row.col.f32.f16.f16.f32 "
        "{%0,%1,%2,%3}, {%4,%5,%6,%7}, {%8,%9}, {%0,%1,%2,%3};\n"
        : "+f"(d[0]), "+f"(d[1]), "+f"(d[2]), "+f"(d[3])
        : "r"(a[0]), "r"(a[1]), "r"(a[2]), "r"(a[3]), "r"(b[0]), "r"(b[1]));
}
__device__ __forceinline__ void ldsm4(uint32_t& r0, uint32_t& r1, uint32_t& r2, uint32_t& r3,
                                      uint32_t addr) {
    asm volatile("ldmatrix.sync.aligned.m8n8.x4.shared.b16 {%0,%1,%2,%3}, [%4];"
                 : "=r"(r0), "=r"(r1), "=r"(r2), "=r"(r3) : "r"(addr));
}
__device__ __forceinline__ void ldsm4t(uint32_t& r0, uint32_t& r1, uint32_t& r2, uint32_t& r3,
                                       uint32_t addr) {
    asm volatile("ldmatrix.sync.aligned.m8n8.x4.trans.shared.b16 {%0,%1,%2,%3}, [%4];"
                 : "=r"(r0), "=r"(r1), "=r"(r2), "=r"(r3) : "r"(addr));
}
__device__ __forceinline__ uint32_t packh2(float a, float b) {
    __half2 h = __floats2half2_rn(a, b);
    uint32_t u;
    *(__half2*)&u = h;
    return u;
}

// ---------------- weight transpose+convert: f32 [K][N] -> half [N][K] (R9 proven) ----------------
__global__ void wconvT_kernel(const float* __restrict__ w, __half* __restrict__ o,
                              int K, int N) {
    __shared__ float t[32][33];
    int bx = blockIdx.x * 32;   // k base
    int by = blockIdx.y * 32;   // n base
    int x = threadIdx.x, y = threadIdx.y;
#pragma unroll
    for (int j = 0; j < 32; j += 8)
        t[y + j][x] = w[(size_t)(bx + y + j) * N + by + x];
    __syncthreads();
#pragma unroll
    for (int j = 0; j < 32; j += 8)
        o[(size_t)(by + y + j) * K + bx + x] = __float2half(t[x][y + j]);
}

// ---------------- adaLN modulation (f32) ----------------
__global__ void mod_kernel(const float* __restrict__ mod,
                           const float* __restrict__ w,
                           const float* __restrict__ b,
                           float* __restrict__ out) {
    __shared__ float sm[C_];
    int batch = blockIdx.y;
    const float* mrow = mod + batch * C_;
    for (int i = threadIdx.x; i < C_; i += blockDim.x) {
        float v = mrow[i];
        sm[i] = v / (1.0f + expf(-v));
    }
    __syncthreads();
    int n = blockIdx.x * blockDim.x + threadIdx.x;
    float acc = b[n];
#pragma unroll 4
    for (int k = 0; k < C_; k++)
        acc += sm[k] * w[k * (6 * C_) + n];
    out[batch * (6 * C_) + n] = acc;
}

// ---------------- LayerNorm + modulation, f32 in, half out ----------------
__global__ void ln_mod_kernel(const float* __restrict__ x, __half* __restrict__ out,
                              const float* __restrict__ mod6, int shiftChunk, int scaleChunk) {
    __shared__ float red[8];
    __shared__ float bc[2];
    int r = blockIdx.x;
    int b = r >> 11;
    const float* xr = x + (size_t)r * C_;
    int t = threadIdx.x;
    float4 v = ((const float4*)xr)[t];
    float s = v.x + v.y + v.z + v.w;
    for (int o = 16; o > 0; o >>= 1) s += __shfl_xor_sync(0xffffffffu, s, o);
    if ((t & 31) == 0) red[t >> 5] = s;
    __syncthreads();
    if (t == 0) {
        float tot = 0.0f;
        for (int i = 0; i < 8; i++) tot += red[i];
        bc[0] = tot * (1.0f / C_);
    }
    __syncthreads();
    float mean = bc[0];
    float dx = v.x - mean, dy = v.y - mean, dz = v.z - mean, dw = v.w - mean;
    float q = dx * dx + dy * dy + dz * dz + dw * dw;
    for (int o = 16; o > 0; o >>= 1) q += __shfl_xor_sync(0xffffffffu, q, o);
    __syncthreads();
    if ((t & 31) == 0) red[t >> 5] = q;
    __syncthreads();
    if (t == 0) {
        float tot = 0.0f;
        for (int i = 0; i < 8; i++) tot += red[i];
        bc[1] = rsqrtf(tot * (1.0f / C_) + 1e-6f);
    }
    __syncthreads();
    float rstd = bc[1];
    const float* mb = mod6 + b * (6 * C_);
    float4 sc = ((const float4*)(mb + scaleChunk * C_))[t];
    float4 sf = ((const float4*)(mb + shiftChunk * C_))[t];
    float n0 = dx * rstd * (1.0f + sc.x) + sf.x;
    float n1 = dy * rstd * (1.0f + sc.y) + sf.y;
    float n2 = dz * rstd * (1.0f + sc.z) + sf.z;
    float n3 = dw * rstd * (1.0f + sc.w) + sf.w;
    uint2 pk;
    pk.x = packh2(n0, n1);
    pk.y = packh2(n2, n3);
    ((uint2*)(out + (size_t)r * C_))[t] = pk;
}

// ---------------- misc ----------------
__device__ __forceinline__ float gelu_f(float x) {
    return 0.5f * x * (1.0f + erff(x * 0.70710678118654752f));
}

__device__ __forceinline__ float exp2s(float s) {
    const float SC = 0.125f * 1.4426950408889634f;
    float tr = fmaf(s, SC, 12582912.0f);
    int n = __float_as_int(tr) - 0x4B400000;
    float f = fmaf(s, SC, 12582912.0f - tr);
    float p = 0.0096181f;
    p = fmaf(p, f, 0.0555041f);
    p = fmaf(p, f, 0.2402265f);
    p = fmaf(p, f, 0.6931472f);
    p = fmaf(p, f, 1.0f);
    return __int_as_float(__float_as_int(p) + (n << 23));
}

// ---------------- flash attention fp16 v3: 3-buffer K/V ring, CP_WAIT(1) ----------------
// smem: K[3][64][36 h2] + V[3][64][36 h2] = 13824 words = 55296 B; 2 CTAs/SM
#define FA_SMEM_BYTES 55296
__global__ void __launch_bounds__(256, 2) flash_kernel(
    const __half* __restrict__ qkv, __half* __restrict__ obuf) {
    extern __shared__ uint32_t sh[];
    int qt = blockIdx.x, bh = blockIdx.y;
    int b = bh >> 4, hd = bh & 15;
    const __half* Qg = qkv + (size_t)b * L_ * (3 * C_) + hd * 64;
    const __half* Kg = Qg + C_;
    const __half* Vg = Qg + 2 * C_;

    int tid = threadIdx.x;
    int w = tid >> 5, lane = tid & 31, g = lane >> 2, tq = lane & 3;
    int wm = w * 16;
    int grp = lane >> 3, rig = lane & 7;
    uint32_t sbase = (uint32_t)__cvta_generic_to_shared(sh);

    uint32_t qf[4][4];
    {
        const uint32_t* q0 = (const uint32_t*)(Qg + (size_t)(qt * 128 + wm + g) * (3 * C_));
        const uint32_t* q1 = (const uint32_t*)(Qg + (size_t)(qt * 128 + wm + g + 8) * (3 * C_));
#pragma unroll
        for (int s = 0; s < 4; s++) {
            qf[s][0] = q0[8 * s + tq];
            qf[s][1] = q1[8 * s + tq];
            qf[s][2] = q0[8 * s + tq + 4];
            qf[s][3] = q1[8 * s + tq + 4];
        }
    }

    // K buffers at [bf*2304], V buffers at [6912 + bf*2304] (words)
#define ISSUE_KV(kt, bf)                                                           \
    {                                                                              \
        _Pragma("unroll")                                                          \
        for (int i = 0; i < 2; i++) {                                              \
            int ci = tid + i * 256;                                                \
            int row = ci >> 3, q = ci & 7;                                         \
            cp16(sbase + ((bf) * 2304 + row * 36 + q * 4) * 4,                     \
                 Kg + (size_t)((kt) * 64 + row) * (3 * C_) + q * 8);               \
        }                                                                          \
        _Pragma("unroll")                                                          \
        for (int i = 0; i < 2; i++) {                                              \
            int ci = tid + i * 256;                                                \
            int row = ci >> 3, q = ci & 7;                                         \
            cp16(sbase + (6912 + (bf) * 2304 + row * 36 + q * 4) * 4,              \
                 Vg + (size_t)((kt) * 64 + row) * (3 * C_) + q * 8);               \
        }                                                                          \
    }

    ISSUE_KV(0, 0); CP_COMMIT();
    ISSUE_KV(1, 1); CP_COMMIT();

    float l0 = 0.0f, l1 = 0.0f;
    float oacc[8][4];
#pragma unroll
    for (int nt = 0; nt < 8; nt++)
#pragma unroll
        for (int j = 0; j < 4; j++) oacc[nt][j] = 0.0f;

    const int NT = L_ / 64;
    int cb = 0;   // compute buffer
    for (int kt = 0; kt < NT; kt++) {
        CP_WAIT(1);            // tile kt landed; tile kt+1 may still be in flight
        __syncthreads();
        if (kt + 2 < NT) {
            int ib = cb + 2; if (ib >= 3) ib -= 3;
            ISSUE_KV(kt + 2, ib);
        }
        CP_COMMIT();

        uint32_t Kb = sbase + (cb * 2304) * 4;
        uint32_t Vb = sbase + (6912 + cb * 2304) * 4;

        float sacc[8][4];
#pragma unroll
        for (int nt = 0; nt < 8; nt++)
#pragma unroll
            for (int j = 0; j < 4; j++) sacc[nt][j] = 0.0f;
#pragma unroll
        for (int s = 0; s < 4; s++) {
#pragma unroll
            for (int p = 0; p < 4; p++) {
                uint32_t b0, b1, b2, b3;
                uint32_t addr = Kb +
                    ((p * 16 + ((grp >> 1) << 3) + rig) * 36 + 8 * s + ((grp & 1) << 2)) * 4;
                ldsm4(b0, b1, b2, b3, addr);
                uint32_t bb0[2] = {b0, b1}, bb1[2] = {b2, b3};
                mma_f16(sacc[2 * p], qf[s], bb0);
                mma_f16(sacc[2 * p + 1], qf[s], bb1);
            }
        }

        uint32_t ph[8][2];
#pragma unroll
        for (int nt = 0; nt < 8; nt++) {
            float p0 = exp2s(sacc[nt][0]);
            float p1 = exp2s(sacc[nt][1]);
            float p2 = exp2s(sacc[nt][2]);
            float p3 = exp2s(sacc[nt][3]);
            l0 += p0 + p1;
            l1 += p2 + p3;
            ph[nt][0] = packh2(p0, p1);
            ph[nt][1] = packh2(p2, p3);
        }

#pragma unroll
        for (int s = 0; s < 4; s++) {
            uint32_t a[4] = {ph[2 * s][0], ph[2 * s][1], ph[2 * s + 1][0], ph[2 * s + 1][1]};
#pragma unroll
            for (int p = 0; p < 4; p++) {
                uint32_t b0, b1, b2, b3;
                uint32_t addr = Vb +
                    ((16 * s + ((grp & 1) << 3) + rig) * 36 + 8 * p + ((grp >> 1) << 2)) * 4;
                ldsm4t(b0, b1, b2, b3, addr);
                uint32_t bb0[2] = {b0, b1}, bb1[2] = {b2, b3};
                mma_f16(oacc[2 * p], a, bb0);
                mma_f16(oacc[2 * p + 1], a, bb1);
            }
        }

        if (++cb == 3) cb = 0;
    }
#undef ISSUE_KV

    l0 += __shfl_xor_sync(0xffffffffu, l0, 1);
    l0 += __shfl_xor_sync(0xffffffffu, l0, 2);
    l1 += __shfl_xor_sync(0xffffffffu, l1, 1);
    l1 += __shfl_xor_sync(0xffffffffu, l1, 2);
    float inv0 = 1.0f / l0, inv1 = 1.0f / l1;
    size_t r0 = (size_t)(b * L_ + qt * 128 + wm + g) * C_ + hd * 64;
    size_t r1 = r0 + (size_t)8 * C_;
#pragma unroll
    for (int nt = 0; nt < 8; nt++) {
        ((uint32_t*)(obuf + r0))[nt * 4 + tq] = packh2(oacc[nt][0] * inv0, oacc[nt][1] * inv0);
        ((uint32_t*)(obuf + r1))[nt * 4 + tq] = packh2(oacc[nt][2] * inv1, oacc[nt][3] * inv1);
    }
}

// ---------------- dense fp16 GEMM (R9 proven): 128x128 CTA, 4 warps, 4 stages, 2 CTAs/SM ----------------
#define STG_W 5120
#define GE_SMEM_BYTES (4 * STG_W * 4)
// EPI: 1 = +bias (half out), 2 = gelu(+bias) (half out), 3 = xin + (acc+bias)*gate (f32 out)
template <int EPI>
__global__ void __launch_bounds__(128, 2) gemm_h(
    const __half* __restrict__ A, const __half* __restrict__ Bw,
    const float* __restrict__ bias, const float* __restrict__ xin,
    const float* __restrict__ gate, void* __restrict__ Cout,
    int N, int K) {
    extern __shared__ uint32_t sh[];
    int bm = blockIdx.y * 128, bn = blockIdx.x * 128;
    int tid = threadIdx.x;
    int w = tid >> 5, lane = tid & 31;
    int wm = (w & 1) * 64, wn = (w >> 1) * 64;
    int g = lane >> 2, tq = lane & 3;
    int grp = lane >> 3, rig = lane & 7;
    uint32_t sbase = (uint32_t)__cvta_generic_to_shared(sh);

#define GISSUE(s, kt)                                                              \
    {                                                                              \
        _Pragma("unroll")                                                          \
        for (int it = 0; it < 4; it++) {                                           \
            int ci = tid + it * 128;                                               \
            int row = ci >> 2, q = ci & 3;                                         \
            cp16(sbase + ((s) * STG_W + row * 20 + q * 4) * 4,                     \
                 A + (size_t)(bm + row) * K + (kt) * 32 + q * 8);                  \
        }                                                                          \
        _Pragma("unroll")                                                          \
        for (int it = 0; it < 4; it++) {                                           \
            int ci = tid + it * 128;                                               \
            int row = ci >> 2, q = ci & 3;                                         \
            cp16(sbase + ((s) * STG_W + 2560 + row * 20 + q * 4) * 4,              \
                 Bw + (size_t)(bn + row) * K + (kt) * 32 + q * 8);                 \
        }                                                                          \
    }

    int nk = K / 32;
    GISSUE(0, 0); CP_COMMIT();
    GISSUE(1, 1); CP_COMMIT();
    GISSUE(2, 2); CP_COMMIT();

    float acc[4][8][4];
#pragma unroll
    for (int i = 0; i < 4; i++)
#pragma unroll
        for (int j = 0; j < 8; j++)
#pragma unroll
            for (int k = 0; k < 4; k++) acc[i][j][k] = 0.0f;

    for (int kt = 0; kt < nk; kt++) {
        int rs = kt & 3;
        CP_WAIT(2);
        __syncthreads();
        if (kt + 3 < nk) { GISSUE((kt + 3) & 3, kt + 3); }
        CP_COMMIT();

        uint32_t stA = sbase + (rs * STG_W) * 4;
        uint32_t stB = stA + 2560 * 4;
#pragma unroll
        for (int s2 = 0; s2 < 2; s2++) {
            uint32_t af[4][4];
#pragma unroll
            for (int mt = 0; mt < 4; mt++) {
                uint32_t addr = stA +
                    ((wm + mt * 16 + ((grp & 1) << 3) + rig) * 20 +
                     8 * s2 + ((grp >> 1) << 2)) * 4;
                ldsm4(af[mt][0], af[mt][1], af[mt][2], af[mt][3], addr);
            }
            uint32_t bf[8][2];
#pragma unroll
            for (int nb = 0; nb < 4; nb++) {
                uint32_t b0, b1, b2, b3;
                uint32_t addr = stB +
                    ((wn + nb * 16 + ((grp >> 1) << 3) + rig) * 20 +
                     8 * s2 + ((grp & 1) << 2)) * 4;
                ldsm4(b0, b1, b2, b3, addr);
                bf[2 * nb][0] = b0; bf[2 * nb][1] = b1;
                bf[2 * nb + 1][0] = b2; bf[2 * nb + 1][1] = b3;
            }
#pragma unroll
            for (int mt = 0; mt < 4; mt++)
#pragma unroll
                for (int nt = 0; nt < 8; nt++)
                    mma_f16(acc[mt][nt], af[mt], bf[nt]);
        }
    }
#undef GISSUE

    // epilogue
#pragma unroll
    for (int mt = 0; mt < 4; mt++) {
#pragma unroll
        for (int i = 0; i < 2; i++) {
            int r = bm + wm + mt * 16 + g + i * 8;
            int bb = r >> 11;
#pragma unroll
            for (int nt = 0; nt < 8; nt++) {
                int c = bn + wn + nt * 8 + tq * 2;
                float v0 = acc[mt][nt][i * 2 + 0] + bias[c];
                float v1 = acc[mt][nt][i * 2 + 1] + bias[c + 1];
                if (EPI == 2) { v0 = gelu_f(v0); v1 = gelu_f(v1); }
                if (EPI == 3) {
                    float* Cf = (float*)Cout;
                    v0 = xin[(size_t)r * N + c]     + v0 * gate[bb * (6 * C_) + c];
                    v1 = xin[(size_t)r * N + c + 1] + v1 * gate[bb * (6 * C_) + c + 1];
                    Cf[(size_t)r * N + c]     = v0;
                    Cf[(size_t)r * N + c + 1] = v1;
                } else {
                    __half* Ch = (__half*)Cout;
                    ((uint32_t*)(Ch + (size_t)r * N))[c >> 1] = packh2(v0, v1);
                }
            }
        }
    }
}

// ---------------- launch ----------------
extern "C" void kernel_launch(void* const* d_in, const int* in_sizes, int n_in,
                              void* d_out, int out_size) {
    const float* feats  = (const float*)d_in[0];
    const float* mod    = (const float*)d_in[1];
    const float* w_mod  = (const float*)d_in[2];
    const float* b_mod  = (const float*)d_in[3];
    const float* w_qkv  = (const float*)d_in[4];
    const float* b_qkv  = (const float*)d_in[5];
    const float* w_proj = (const float*)d_in[6];
    const float* b_proj = (const float*)d_in[7];
    const float* w_fc1  = (const float*)d_in[8];
    const float* b_fc1  = (const float*)d_in[9];
    const float* w_fc2  = (const float*)d_in[10];
    const float* b_fc2  = (const float*)d_in[11];
    float* out = (float*)d_out;

    float* mod6; __half* h; __half* qkv; __half* obuf; float* xbuf; __half* gbuf;
    __half* wh;
    cudaGetSymbolAddress((void**)&mod6, g_mod6);
    cudaGetSymbolAddress((void**)&h,    g_h);
    cudaGetSymbolAddress((void**)&qkv,  g_qkv);
    cudaGetSymbolAddress((void**)&obuf, g_o);
    cudaGetSymbolAddress((void**)&xbuf, g_x);
    cudaGetSymbolAddress((void**)&gbuf, g_g);
    cudaGetSymbolAddress((void**)&wh,   g_wh);

    __half* wqkvh = wh;                         // [3072][1024]
    __half* wprojh = wqkvh + 3 * C_ * C_;       // [1024][1024]
    __half* wfc1h  = wprojh + C_ * C_;          // [4096][1024]
    __half* wfc2h  = wfc1h + 4 * C_ * C_;       // [1024][4096]

    cudaFuncSetAttribute(flash_kernel, cudaFuncAttributeMaxDynamicSharedMemorySize, FA_SMEM_BYTES);
    cudaFuncSetAttribute(gemm_h<1>, cudaFuncAttributeMaxDynamicSharedMemorySize, GE_SMEM_BYTES);
    cudaFuncSetAttribute(gemm_h<2>, cudaFuncAttributeMaxDynamicSharedMemorySize, GE_SMEM_BYTES);
    cudaFuncSetAttribute(gemm_h<3>, cudaFuncAttributeMaxDynamicSharedMemorySize, GE_SMEM_BYTES);

    // 0. weight transpose+convert to half [N][K] (R9 proven: separate launches, default stream)
    wconvT_kernel<<<dim3(C_ / 32, 3 * C_ / 32), dim3(32, 8)>>>(w_qkv, wqkvh, C_, 3 * C_);
    wconvT_kernel<<<dim3(C_ / 32, C_ / 32), dim3(32, 8)>>>(w_proj, wprojh, C_, C_);
    wconvT_kernel<<<dim3(C_ / 32, 4 * C_ / 32), dim3(32, 8)>>>(w_fc1, wfc1h, C_, 4 * C_);
    wconvT_kernel<<<dim3(4 * C_ / 32, C_ / 32), dim3(32, 8)>>>(w_fc2, wfc2h, 4 * C_, C_);

    // 1. adaLN modulation vector
    mod_kernel<<<dim3(6 * C_ / 256, B_), 256>>>(mod, w_mod, b_mod, mod6);

    // 2. LN1 + (shift_a, scale_a) -> half
    ln_mod_kernel<<<M_, 256>>>(feats, h, mod6, 0, 1);

    // 3. qkv = h @ w_qkv + b_qkv -> half
    gemm_h<1><<<dim3(24, 32), 128, GE_SMEM_BYTES>>>(
        h, wqkvh, b_qkv, nullptr, nullptr, qkv, 3 * C_, C_);

    // 4. fused flash attention -> obuf (half); 3-buffer pipeline
    flash_kernel<<<dim3(16, 32), 256, FA_SMEM_BYTES>>>(qkv, obuf);

    // 5. x = feats + (O @ w_proj + b_proj) * gate_a -> f32
    gemm_h<3><<<dim3(8, 32), 128, GE_SMEM_BYTES>>>(
        obuf, wprojh, b_proj, feats, mod6 + 2 * C_, xbuf, C_, C_);

    // 6. LN2 + (shift_m, scale_m) -> half
    ln_mod_kernel<<<M_, 256>>>(xbuf, h, mod6, 3, 4);

    // 7. g = gelu(h @ w_fc1 + b_fc1) -> half
    gemm_h<2><<<dim3(32, 32), 128, GE_SMEM_BYTES>>>(
        h, wfc1h, b_fc1, nullptr, nullptr, gbuf, 4 * C_, C_);

    // 8. out = x + (g @ w_fc2 + b_fc2) * gate_m -> f32
    gemm_h<3><<<dim3(8, 32), 128, GE_SMEM_BYTES>>>(
        gbuf, wfc2h, b_fc2, xbuf, mod6 + 5 * C_, out, C_, 4 * C_);
}

// round 15
// speedup vs baseline: 1.0420x; 1.0420x over previous
#include <cuda_runtime.h>
#include <cuda_fp16.h>
#include <math.h>
#include <stdint.h>

#define B_ 2
#define L_ 2048
#define C_ 1024
#define H_ 16
#define M_ 4096   // B_*L_

// ---------------- scratch (static device globals; no allocation) ----------------
__device__ float    g_mod6[B_ * 6 * C_];
__device__ __half   g_h[M_ * C_];          // LN outputs (half)
__device__ __half   g_qkv[M_ * 3 * C_];    // qkv (half)
__device__ __half   g_o[M_ * C_];          // attention out (half)
__device__ float    g_x[M_ * C_];          // residual stream (f32)
__device__ __half   g_g[M_ * 4 * C_];      // fc1 out (half)
__device__ __half   g_wh[12 * C_ * C_];    // transposed half weights [N][K]

// ---------------- cp.async helpers ----------------
__device__ __forceinline__ void cp16(uint32_t dst, const void* src) {
    asm volatile("cp.async.cg.shared.global [%0], [%1], 16;\n" :: "r"(dst), "l"(src));
}
#define CP_COMMIT() asm volatile("cp.async.commit_group;\n" ::: "memory")
#define CP_WAIT(n)  asm volatile("cp.async.wait_group %0;\n" :: "n"(n) : "memory")

// ---------------- mma / ldmatrix helpers ----------------
__device__ __forceinline__ void mma_f16(float* d, const uint32_t* a, const uint32_t* b) {
    asm volatile(
        "mma.sync.aligned.m16n8k16.row.col.f32.f16.f16.f32 "
        "{%0,%1,%2,%3}, {%4,%5,%6,%7}, {%8,%9}, {%0,%1,%2,%3};\n"
        : "+f"(d[0]), "+f"(d[1]), "+f"(d[2]), "+f"(d[3])
        : "r"(a[0]), "r"(a[1]), "r"(a[2]), "r"(a[3]), "r"(b[0]), "r"(b[1]));
}
__device__ __forceinline__ void ldsm4(uint32_t& r0, uint32_t& r1, uint32_t& r2, uint32_t& r3,
                                      uint32_t addr) {
    asm volatile("ldmatrix.sync.aligned.m8n8.x4.shared.b16 {%0,%1,%2,%3}, [%4];"
                 : "=r"(r0), "=r"(r1), "=r"(r2), "=r"(r3) : "r"(addr));
}
__device__ __forceinline__ void ldsm4t(uint32_t& r0, uint32_t& r1, uint32_t& r2, uint32_t& r3,
                                       uint32_t addr) {
    asm volatile("ldmatrix.sync.aligned.m8n8.x4.trans.shared.b16 {%0,%1,%2,%3}, [%4];"
                 : "=r"(r0), "=r"(r1), "=r"(r2), "=r"(r3) : "r"(addr));
}
__device__ __forceinline__ uint32_t packh2(float a, float b) {
    __half2 h = __floats2half2_rn(a, b);
    uint32_t u;
    *(__half2*)&u = h;
    return u;
}

// ---------------- weight transpose+convert: f32 [K][N] -> half [N][K] (R9 proven) ----------------
__global__ void wconvT_kernel(const float* __restrict__ w, __half* __restrict__ o,
                              int K, int N) {
    __shared__ float t[32][33];
    int bx = blockIdx.x * 32;   // k base
    int by = blockIdx.y * 32;   // n base
    int x = threadIdx.x, y = threadIdx.y;
#pragma unroll
    for (int j = 0; j < 32; j += 8)
        t[y + j][x] = w[(size_t)(bx + y + j) * N + by + x];
    __syncthreads();
#pragma unroll
    for (int j = 0; j < 32; j += 8)
        o[(size_t)(by + y + j) * K + bx + x] = __float2half(t[x][y + j]);
}

// ---------------- adaLN modulation (f32) ----------------
__global__ void mod_kernel(const float* __restrict__ mod,
                           const float* __restrict__ w,
                           const float* __restrict__ b,
                           float* __restrict__ out) {
    __shared__ float sm[C_];
    int batch = blockIdx.y;
    const float* mrow = mod + batch * C_;
    for (int i = threadIdx.x; i < C_; i += blockDim.x) {
        float v = mrow[i];
        sm[i] = v / (1.0f + expf(-v));
    }
    __syncthreads();
    int n = blockIdx.x * blockDim.x + threadIdx.x;
    float acc = b[n];
#pragma unroll 4
    for (int k = 0; k < C_; k++)
        acc += sm[k] * w[k * (6 * C_) + n];
    out[batch * (6 * C_) + n] = acc;
}

// ---------------- LayerNorm + modulation v2: one warp per row, no barriers ----------------
// grid: M_/8 blocks x 256 threads (8 warps, 1 row each). f32 in, half out.
__global__ void __launch_bounds__(256) ln_mod_kernel(
    const float* __restrict__ x, __half* __restrict__ out,
    const float* __restrict__ mod6, int shiftChunk, int scaleChunk) {
    int wid = threadIdx.x >> 5, lane = threadIdx.x & 31;
    int r = blockIdx.x * 8 + wid;
    int b = r >> 11;
    const float4* row4 = (const float4*)(x + (size_t)r * C_);

    float4 v[8];
    float s = 0.0f;
#pragma unroll
    for (int i = 0; i < 8; i++) {
        v[i] = row4[i * 32 + lane];
        s += v[i].x + v[i].y + v[i].z + v[i].w;
    }
#pragma unroll
    for (int o = 16; o > 0; o >>= 1) s += __shfl_xor_sync(0xffffffffu, s, o);
    float mean = s * (1.0f / C_);

    float q = 0.0f;
#pragma unroll
    for (int i = 0; i < 8; i++) {
        float dx = v[i].x - mean, dy = v[i].y - mean;
        float dz = v[i].z - mean, dw = v[i].w - mean;
        q += dx * dx + dy * dy + dz * dz + dw * dw;
    }
#pragma unroll
    for (int o = 16; o > 0; o >>= 1) q += __shfl_xor_sync(0xffffffffu, q, o);
    float rstd = rsqrtf(q * (1.0f / C_) + 1e-6f);

    const float4* sc4 = (const float4*)(mod6 + b * (6 * C_) + scaleChunk * C_);
    const float4* sf4 = (const float4*)(mod6 + b * (6 * C_) + shiftChunk * C_);
    uint2* o2 = (uint2*)(out + (size_t)r * C_);
#pragma unroll
    for (int i = 0; i < 8; i++) {
        float4 sc = sc4[i * 32 + lane];
        float4 sf = sf4[i * 32 + lane];
        float n0 = (v[i].x - mean) * rstd * (1.0f + sc.x) + sf.x;
        float n1 = (v[i].y - mean) * rstd * (1.0f + sc.y) + sf.y;
        float n2 = (v[i].z - mean) * rstd * (1.0f + sc.z) + sf.z;
        float n3 = (v[i].w - mean) * rstd * (1.0f + sc.w) + sf.w;
        uint2 pk;
        pk.x = packh2(n0, n1);
        pk.y = packh2(n2, n3);
        o2[i * 32 + lane] = pk;
    }
}

// ---------------- misc ----------------
__device__ __forceinline__ float gelu_f(float x) {
    return 0.5f * x * (1.0f + erff(x * 0.70710678118654752f));
}

__device__ __forceinline__ float exp2s(float s) {
    const float SC = 0.125f * 1.4426950408889634f;
    float tr = fmaf(s, SC, 12582912.0f);
    int n = __float_as_int(tr) - 0x4B400000;
    float f = fmaf(s, SC, 12582912.0f - tr);
    float p = 0.0096181f;
    p = fmaf(p, f, 0.0555041f);
    p = fmaf(p, f, 0.2402265f);
    p = fmaf(p, f, 0.6931472f);
    p = fmaf(p, f, 1.0f);
    return __int_as_float(__float_as_int(p) + (n << 23));
}

// ---------------- flash attention fp16 (R8/R9 exact, proven) ----------------
#define FA_SMEM_BYTES 36864
__global__ void __launch_bounds__(256, 2) flash_kernel(
    const __half* __restrict__ qkv, __half* __restrict__ obuf) {
    extern __shared__ uint32_t sh[];
    int qt = blockIdx.x, bh = blockIdx.y;
    int b = bh >> 4, hd = bh & 15;
    const __half* Qg = qkv + (size_t)b * L_ * (3 * C_) + hd * 64;
    const __half* Kg = Qg + C_;
    const __half* Vg = Qg + 2 * C_;

    int tid = threadIdx.x;
    int w = tid >> 5, lane = tid & 31, g = lane >> 2, tq = lane & 3;
    int wm = w * 16;
    int grp = lane >> 3, rig = lane & 7;
    uint32_t sbase = (uint32_t)__cvta_generic_to_shared(sh);

    uint32_t qf[4][4];
    {
        const uint32_t* q0 = (const uint32_t*)(Qg + (size_t)(qt * 128 + wm + g) * (3 * C_));
        const uint32_t* q1 = (const uint32_t*)(Qg + (size_t)(qt * 128 + wm + g + 8) * (3 * C_));
#pragma unroll
        for (int s = 0; s < 4; s++) {
            qf[s][0] = q0[8 * s + tq];
            qf[s][1] = q1[8 * s + tq];
            qf[s][2] = q0[8 * s + tq + 4];
            qf[s][3] = q1[8 * s + tq + 4];
        }
    }

#define ISSUE_KV(kt, bf)                                                           \
    {                                                                              \
        _Pragma("unroll")                                                          \
        for (int i = 0; i < 2; i++) {                                              \
            int ci = tid + i * 256;                                                \
            int row = ci >> 3, q = ci & 7;                                         \
            cp16(sbase + ((bf) * 2304 + row * 36 + q * 4) * 4,                     \
                 Kg + (size_t)((kt) * 64 + row) * (3 * C_) + q * 8);               \
        }                                                                          \
        _Pragma("unroll")                                                          \
        for (int i = 0; i < 2; i++) {                                              \
            int ci = tid + i * 256;                                                \
            int row = ci >> 3, q = ci & 7;                                         \
            cp16(sbase + (4608 + (bf) * 2304 + row * 36 + q * 4) * 4,              \
                 Vg + (size_t)((kt) * 64 + row) * (3 * C_) + q * 8);               \
        }                                                                          \
    }

    ISSUE_KV(0, 0);
    CP_COMMIT();

    float l0 = 0.0f, l1 = 0.0f;
    float oacc[8][4];
#pragma unroll
    for (int nt = 0; nt < 8; nt++)
#pragma unroll
        for (int j = 0; j < 4; j++) oacc[nt][j] = 0.0f;

    for (int kt = 0; kt < L_ / 64; kt++) {
        int bf = kt & 1;
        CP_WAIT(0);
        __syncthreads();
        if (kt + 1 < L_ / 64) { ISSUE_KV(kt + 1, bf ^ 1); }
        CP_COMMIT();

        uint32_t Kb = sbase + (bf * 2304) * 4;
        uint32_t Vb = sbase + (4608 + bf * 2304) * 4;

        float sacc[8][4];
#pragma unroll
        for (int nt = 0; nt < 8; nt++)
#pragma unroll
            for (int j = 0; j < 4; j++) sacc[nt][j] = 0.0f;
#pragma unroll
        for (int s = 0; s < 4; s++) {
#pragma unroll
            for (int p = 0; p < 4; p++) {
                uint32_t b0, b1, b2, b3;
                uint32_t addr = Kb +
                    ((p * 16 + ((grp >> 1) << 3) + rig) * 36 + 8 * s + ((grp & 1) << 2)) * 4;
                ldsm4(b0, b1, b2, b3, addr);
                uint32_t bb0[2] = {b0, b1}, bb1[2] = {b2, b3};
                mma_f16(sacc[2 * p], qf[s], bb0);
                mma_f16(sacc[2 * p + 1], qf[s], bb1);
            }
        }

        uint32_t ph[8][2];
#pragma unroll
        for (int nt = 0; nt < 8; nt++) {
            float p0 = exp2s(sacc[nt][0]);
            float p1 = exp2s(sacc[nt][1]);
            float p2 = exp2s(sacc[nt][2]);
            float p3 = exp2s(sacc[nt][3]);
            l0 += p0 + p1;
            l1 += p2 + p3;
            ph[nt][0] = packh2(p0, p1);
            ph[nt][1] = packh2(p2, p3);
        }

#pragma unroll
        for (int s = 0; s < 4; s++) {
            uint32_t a[4] = {ph[2 * s][0], ph[2 * s][1], ph[2 * s + 1][0], ph[2 * s + 1][1]};
#pragma unroll
            for (int p = 0; p < 4; p++) {
                uint32_t b0, b1, b2, b3;
                uint32_t addr = Vb +
                    ((16 * s + ((grp & 1) << 3) + rig) * 36 + 8 * p + ((grp >> 1) << 2)) * 4;
                ldsm4t(b0, b1, b2, b3, addr);
                uint32_t bb0[2] = {b0, b1}, bb1[2] = {b2, b3};
                mma_f16(oacc[2 * p], a, bb0);
                mma_f16(oacc[2 * p + 1], a, bb1);
            }
        }
    }
#undef ISSUE_KV

    l0 += __shfl_xor_sync(0xffffffffu, l0, 1);
    l0 += __shfl_xor_sync(0xffffffffu, l0, 2);
    l1 += __shfl_xor_sync(0xffffffffu, l1, 1);
    l1 += __shfl_xor_sync(0xffffffffu, l1, 2);
    float inv0 = 1.0f / l0, inv1 = 1.0f / l1;
    size_t r0 = (size_t)(b * L_ + qt * 128 + wm + g) * C_ + hd * 64;
    size_t r1 = r0 + (size_t)8 * C_;
#pragma unroll
    for (int nt = 0; nt < 8; nt++) {
        ((uint32_t*)(obuf + r0))[nt * 4 + tq] = packh2(oacc[nt][0] * inv0, oacc[nt][1] * inv0);
        ((uint32_t*)(obuf + r1))[nt * 4 + tq] = packh2(oacc[nt][2] * inv1, oacc[nt][3] * inv1);
    }
}

// ---------------- dense fp16 GEMM (R9 proven): 128x128 CTA, 4 warps, 4 stages, 2 CTAs/SM ----------------
#define STG_W 5120
#define GE_SMEM_BYTES (4 * STG_W * 4)
// EPI: 1 = +bias (half out), 2 = gelu(+bias) (half out), 3 = xin + (acc+bias)*gate (f32 out)
template <int EPI>
__global__ void __launch_bounds__(128, 2) gemm_h(
    const __half* __restrict__ A, const __half* __restrict__ Bw,
    const float* __restrict__ bias, const float* __restrict__ xin,
    const float* __restrict__ gate, void* __restrict__ Cout,
    int N, int K) {
    extern __shared__ uint32_t sh[];
    int bm = blockIdx.y * 128, bn = blockIdx.x * 128;
    int tid = threadIdx.x;
    int w = tid >> 5, lane = tid & 31;
    int wm = (w & 1) * 64, wn = (w >> 1) * 64;
    int g = lane >> 2, tq = lane & 3;
    int grp = lane >> 3, rig = lane & 7;
    uint32_t sbase = (uint32_t)__cvta_generic_to_shared(sh);

#define GISSUE(s, kt)                                                              \
    {                                                                              \
        _Pragma("unroll")                                                          \
        for (int it = 0; it < 4; it++) {                                           \
            int ci = tid + it * 128;                                               \
            int row = ci >> 2, q = ci & 3;                                         \
            cp16(sbase + ((s) * STG_W + row * 20 + q * 4) * 4,                     \
                 A + (size_t)(bm + row) * K + (kt) * 32 + q * 8);                  \
        }                                                                          \
        _Pragma("unroll")                                                          \
        for (int it = 0; it < 4; it++) {                                           \
            int ci = tid + it * 128;                                               \
            int row = ci >> 2, q = ci & 3;                                         \
            cp16(sbase + ((s) * STG_W + 2560 + row * 20 + q * 4) * 4,              \
                 Bw + (size_t)(bn + row) * K + (kt) * 32 + q * 8);                 \
        }                                                                          \
    }

    int nk = K / 32;
    GISSUE(0, 0); CP_COMMIT();
    GISSUE(1, 1); CP_COMMIT();
    GISSUE(2, 2); CP_COMMIT();

    float acc[4][8][4];
#pragma unroll
    for (int i = 0; i < 4; i++)
#pragma unroll
        for (int j = 0; j < 8; j++)
#pragma unroll
            for (int k = 0; k < 4; k++) acc[i][j][k] = 0.0f;

    for (int kt = 0; kt < nk; kt++) {
        int rs = kt & 3;
        CP_WAIT(2);
        __syncthreads();
        if (kt + 3 < nk) { GISSUE((kt + 3) & 3, kt + 3); }
        CP_COMMIT();

        uint32_t stA = sbase + (rs * STG_W) * 4;
        uint32_t stB = stA + 2560 * 4;
#pragma unroll
        for (int s2 = 0; s2 < 2; s2++) {
            uint32_t af[4][4];
#pragma unroll
            for (int mt = 0; mt < 4; mt++) {
                uint32_t addr = stA +
                    ((wm + mt * 16 + ((grp & 1) << 3) + rig) * 20 +
                     8 * s2 + ((grp >> 1) << 2)) * 4;
                ldsm4(af[mt][0], af[mt][1], af[mt][2], af[mt][3], addr);
            }
            uint32_t bf[8][2];
#pragma unroll
            for (int nb = 0; nb < 4; nb++) {
                uint32_t b0, b1, b2, b3;
                uint32_t addr = stB +
                    ((wn + nb * 16 + ((grp >> 1) << 3) + rig) * 20 +
                     8 * s2 + ((grp & 1) << 2)) * 4;
                ldsm4(b0, b1, b2, b3, addr);
                bf[2 * nb][0] = b0; bf[2 * nb][1] = b1;
                bf[2 * nb + 1][0] = b2; bf[2 * nb + 1][1] = b3;
            }
#pragma unroll
            for (int mt = 0; mt < 4; mt++)
#pragma unroll
                for (int nt = 0; nt < 8; nt++)
                    mma_f16(acc[mt][nt], af[mt], bf[nt]);
        }
    }
#undef GISSUE

    // epilogue
#pragma unroll
    for (int mt = 0; mt < 4; mt++) {
#pragma unroll
        for (int i = 0; i < 2; i++) {
            int r = bm + wm + mt * 16 + g + i * 8;
            int bb = r >> 11;
#pragma unroll
            for (int nt = 0; nt < 8; nt++) {
                int c = bn + wn + nt * 8 + tq * 2;
                float v0 = acc[mt][nt][i * 2 + 0] + bias[c];
                float v1 = acc[mt][nt][i * 2 + 1] + bias[c + 1];
                if (EPI == 2) { v0 = gelu_f(v0); v1 = gelu_f(v1); }
                if (EPI == 3) {
                    float* Cf = (float*)Cout;
                    v0 = xin[(size_t)r * N + c]     + v0 * gate[bb * (6 * C_) + c];
                    v1 = xin[(size_t)r * N + c + 1] + v1 * gate[bb * (6 * C_) + c + 1];
                    Cf[(size_t)r * N + c]     = v0;
                    Cf[(size_t)r * N + c + 1] = v1;
                } else {
                    __half* Ch = (__half*)Cout;
                    ((uint32_t*)(Ch + (size_t)r * N))[c >> 1] = packh2(v0, v1);
                }
            }
        }
    }
}

// ---------------- launch ----------------
extern "C" void kernel_launch(void* const* d_in, const int* in_sizes, int n_in,
                              void* d_out, int out_size) {
    const float* feats  = (const float*)d_in[0];
    const float* mod    = (const float*)d_in[1];
    const float* w_mod  = (const float*)d_in[2];
    const float* b_mod  = (const float*)d_in[3];
    const float* w_qkv  = (const float*)d_in[4];
    const float* b_qkv  = (const float*)d_in[5];
    const float* w_proj = (const float*)d_in[6];
    const float* b_proj = (const float*)d_in[7];
    const float* w_fc1  = (const float*)d_in[8];
    const float* b_fc1  = (const float*)d_in[9];
    const float* w_fc2  = (const float*)d_in[10];
    const float* b_fc2  = (const float*)d_in[11];
    float* out = (float*)d_out;

    float* mod6; __half* h; __half* qkv; __half* obuf; float* xbuf; __half* gbuf;
    __half* wh;
    cudaGetSymbolAddress((void**)&mod6, g_mod6);
    cudaGetSymbolAddress((void**)&h,    g_h);
    cudaGetSymbolAddress((void**)&qkv,  g_qkv);
    cudaGetSymbolAddress((void**)&obuf, g_o);
    cudaGetSymbolAddress((void**)&xbuf, g_x);
    cudaGetSymbolAddress((void**)&gbuf, g_g);
    cudaGetSymbolAddress((void**)&wh,   g_wh);

    __half* wqkvh = wh;                         // [3072][1024]
    __half* wprojh = wqkvh + 3 * C_ * C_;       // [1024][1024]
    __half* wfc1h  = wprojh + C_ * C_;          // [4096][1024]
    __half* wfc2h  = wfc1h + 4 * C_ * C_;       // [1024][4096]

    cudaFuncSetAttribute(flash_kernel, cudaFuncAttributeMaxDynamicSharedMemorySize, FA_SMEM_BYTES);
    cudaFuncSetAttribute(gemm_h<1>, cudaFuncAttributeMaxDynamicSharedMemorySize, GE_SMEM_BYTES);
    cudaFuncSetAttribute(gemm_h<2>, cudaFuncAttributeMaxDynamicSharedMemorySize, GE_SMEM_BYTES);
    cudaFuncSetAttribute(gemm_h<3>, cudaFuncAttributeMaxDynamicSharedMemorySize, GE_SMEM_BYTES);

    // 0. weight transpose+convert to half [N][K] (R9 proven: separate launches, default stream)
    wconvT_kernel<<<dim3(C_ / 32, 3 * C_ / 32), dim3(32, 8)>>>(w_qkv, wqkvh, C_, 3 * C_);
    wconvT_kernel<<<dim3(C_ / 32, C_ / 32), dim3(32, 8)>>>(w_proj, wprojh, C_, C_);
    wconvT_kernel<<<dim3(C_ / 32, 4 * C_ / 32), dim3(32, 8)>>>(w_fc1, wfc1h, C_, 4 * C_);
    wconvT_kernel<<<dim3(4 * C_ / 32, C_ / 32), dim3(32, 8)>>>(w_fc2, wfc2h, 4 * C_, C_);

    // 1. adaLN modulation vector
    mod_kernel<<<dim3(6 * C_ / 256, B_), 256>>>(mod, w_mod, b_mod, mod6);

    // 2. LN1 + (shift_a, scale_a) -> half (warp-per-row)
    ln_mod_kernel<<<M_ / 8, 256>>>(feats, h, mod6, 0, 1);

    // 3. qkv = h @ w_qkv + b_qkv -> half
    gemm_h<1><<<dim3(24, 32), 128, GE_SMEM_BYTES>>>(
        h, wqkvh, b_qkv, nullptr, nullptr, qkv, 3 * C_, C_);

    // 4. fused flash attention -> obuf (half)
    flash_kernel<<<dim3(16, 32), 256, FA_SMEM_BYTES>>>(qkv, obuf);

    // 5. x = feats + (O @ w_proj + b_proj) * gate_a -> f32
    gemm_h<3><<<dim3(8, 32), 128, GE_SMEM_BYTES>>>(
        obuf, wprojh, b_proj, feats, mod6 + 2 * C_, xbuf, C_, C_);

    // 6. LN2 + (shift_m, scale_m) -> half (warp-per-row)
    ln_mod_kernel<<<M_ / 8, 256>>>(xbuf, h, mod6, 3, 4);

    // 7. g = gelu(h @ w_fc1 + b_fc1) -> half
    gemm_h<2><<<dim3(32, 32), 128, GE_SMEM_BYTES>>>(
        h, wfc1h, b_fc1, nullptr, nullptr, gbuf, 4 * C_, C_);

    // 8. out = x + (g @ w_fc2 + b_fc2) * gate_m -> f32
    gemm_h<3><<<dim3(8, 32), 128, GE_SMEM_BYTES>>>(
        gbuf, wfc2h, b_fc2, xbuf, mod6 + 5 * C_, out, C_, 4 * C_);
}

// round 16
// speedup vs baseline: 1.2061x; 1.1575x over previous
#include <cuda_runtime.h>
#include <cuda_fp16.h>
#include <math.h>
#include <stdint.h>

#define B_ 2
#define L_ 2048
#define C_ 1024
#define H_ 16
#define M_ 4096   // B_*L_

// ---------------- scratch (static device globals; no allocation) ----------------
__device__ float    g_mod6[B_ * 6 * C_];
__device__ __half   g_h[M_ * C_];          // LN outputs (half)
__device__ __half   g_qkv[M_ * 3 * C_];    // qkv (half)
__device__ __half   g_o[M_ * C_];          // attention out (half)
__device__ float    g_x[M_ * C_];          // residual stream (f32)
__device__ __half   g_g[M_ * 4 * C_];      // fc1 out (half)
__device__ __half   g_wh[12 * C_ * C_];    // transposed half weights [N][K]

// ---------------- cp.async helpers ----------------
__device__ __forceinline__ void cp16(uint32_t dst, const void* src) {
    asm volatile("cp.async.cg.shared.global [%0], [%1], 16;\n" :: "r"(dst), "l"(src));
}
#define CP_COMMIT() asm volatile("cp.async.commit_group;\n" ::: "memory")
#define CP_WAIT(n)  asm volatile("cp.async.wait_group %0;\n" :: "n"(n) : "memory")

// ---------------- mma / ldmatrix helpers ----------------
__device__ __forceinline__ void mma_f16(float* d, const uint32_t* a, const uint32_t* b) {
    asm volatile(
        "mma.sync.aligned.m16n8k16.row.col.f32.f16.f16.f32 "
        "{%0,%1,%2,%3}, {%4,%5,%6,%7}, {%8,%9}, {%0,%1,%2,%3};\n"
        : "+f"(d[0]), "+f"(d[1]), "+f"(d[2]), "+f"(d[3])
        : "r"(a[0]), "r"(a[1]), "r"(a[2]), "r"(a[3]), "r"(b[0]), "r"(b[1]));
}
__device__ __forceinline__ void ldsm4(uint32_t& r0, uint32_t& r1, uint32_t& r2, uint32_t& r3,
                                      uint32_t addr) {
    asm volatile("ldmatrix.sync.aligned.m8n8.x4.shared.b16 {%0,%1,%2,%3}, [%4];"
                 : "=r"(r0), "=r"(r1), "=r"(r2), "=r"(r3) : "r"(addr));
}
__device__ __forceinline__ void ldsm4t(uint32_t& r0, uint32_t& r1, uint32_t& r2, uint32_t& r3,
                                       uint32_t addr) {
    asm volatile("ldmatrix.sync.aligned.m8n8.x4.trans.shared.b16 {%0,%1,%2,%3}, [%4];"
                 : "=r"(r0), "=r"(r1), "=r"(r2), "=r"(r3) : "r"(addr));
}
__device__ __forceinline__ uint32_t packh2(float a, float b) {
    __half2 h = __floats2half2_rn(a, b);
    uint32_t u;
    *(__half2*)&u = h;
    return u;
}

// ---------------- weight transpose+convert: f32 [K][N] -> half [N][K] (R9 proven) ----------------
__global__ void wconvT_kernel(const float* __restrict__ w, __half* __restrict__ o,
                              int K, int N) {
    __shared__ float t[32][33];
    int bx = blockIdx.x * 32;   // k base
    int by = blockIdx.y * 32;   // n base
    int x = threadIdx.x, y = threadIdx.y;
#pragma unroll
    for (int j = 0; j < 32; j += 8)
        t[y + j][x] = w[(size_t)(bx + y + j) * N + by + x];
    __syncthreads();
#pragma unroll
    for (int j = 0; j < 32; j += 8)
        o[(size_t)(by + y + j) * K + bx + x] = __float2half(t[x][y + j]);
}

// ---------------- adaLN modulation v2: split-K x4, 64 outputs/block ----------------
// grid (6C/64, B_), 256 threads. thread: n = t&63, kc = t>>6 (0..3, 256 k each)
__global__ void __launch_bounds__(256) mod_kernel(
    const float* __restrict__ mod, const float* __restrict__ w,
    const float* __restrict__ b, float* __restrict__ out) {
    __shared__ float sm[C_];
    __shared__ float part[4][64];
    int batch = blockIdx.y;
    const float* mrow = mod + batch * C_;
    for (int i = threadIdx.x; i < C_; i += 256) {
        float v = mrow[i];
        sm[i] = v / (1.0f + expf(-v));
    }
    __syncthreads();
    int t = threadIdx.x;
    int nl = t & 63, kc = t >> 6;
    int n = blockIdx.x * 64 + nl;
    const float* wp = w + (size_t)(kc * 256) * (6 * C_) + n;
    float acc = 0.0f;
#pragma unroll 4
    for (int k = 0; k < 256; k++)
        acc += sm[kc * 256 + k] * wp[(size_t)k * (6 * C_)];
    part[kc][nl] = acc;
    __syncthreads();
    if (kc == 0) {
        float tot = part[0][nl] + part[1][nl] + part[2][nl] + part[3][nl] + b[n];
        out[batch * (6 * C_) + n] = tot;
    }
}

// ---------------- LayerNorm + modulation: one warp per row, no barriers (R15 proven) ----------------
__global__ void __launch_bounds__(256) ln_mod_kernel(
    const float* __restrict__ x, __half* __restrict__ out,
    const float* __restrict__ mod6, int shiftChunk, int scaleChunk) {
    int wid = threadIdx.x >> 5, lane = threadIdx.x & 31;
    int r = blockIdx.x * 8 + wid;
    int b = r >> 11;
    const float4* row4 = (const float4*)(x + (size_t)r * C_);

    float4 v[8];
    float s = 0.0f;
#pragma unroll
    for (int i = 0; i < 8; i++) {
        v[i] = row4[i * 32 + lane];
        s += v[i].x + v[i].y + v[i].z + v[i].w;
    }
#pragma unroll
    for (int o = 16; o > 0; o >>= 1) s += __shfl_xor_sync(0xffffffffu, s, o);
    float mean = s * (1.0f / C_);

    float q = 0.0f;
#pragma unroll
    for (int i = 0; i < 8; i++) {
        float dx = v[i].x - mean, dy = v[i].y - mean;
        float dz = v[i].z - mean, dw = v[i].w - mean;
        q += dx * dx + dy * dy + dz * dz + dw * dw;
    }
#pragma unroll
    for (int o = 16; o > 0; o >>= 1) q += __shfl_xor_sync(0xffffffffu, q, o);
    float rstd = rsqrtf(q * (1.0f / C_) + 1e-6f);

    const float4* sc4 = (const float4*)(mod6 + b * (6 * C_) + scaleChunk * C_);
    const float4* sf4 = (const float4*)(mod6 + b * (6 * C_) + shiftChunk * C_);
    uint2* o2 = (uint2*)(out + (size_t)r * C_);
#pragma unroll
    for (int i = 0; i < 8; i++) {
        float4 sc = sc4[i * 32 + lane];
        float4 sf = sf4[i * 32 + lane];
        float n0 = (v[i].x - mean) * rstd * (1.0f + sc.x) + sf.x;
        float n1 = (v[i].y - mean) * rstd * (1.0f + sc.y) + sf.y;
        float n2 = (v[i].z - mean) * rstd * (1.0f + sc.z) + sf.z;
        float n3 = (v[i].w - mean) * rstd * (1.0f + sc.w) + sf.w;
        uint2 pk;
        pk.x = packh2(n0, n1);
        pk.y = packh2(n2, n3);
        o2[i * 32 + lane] = pk;
    }
}

// ---------------- misc ----------------
__device__ __forceinline__ float gelu_f(float x) {
    return 0.5f * x * (1.0f + erff(x * 0.70710678118654752f));
}

__device__ __forceinline__ float exp2s(float s) {
    const float SC = 0.125f * 1.4426950408889634f;
    float tr = fmaf(s, SC, 12582912.0f);
    int n = __float_as_int(tr) - 0x4B400000;
    float f = fmaf(s, SC, 12582912.0f - tr);
    float p = 0.0096181f;
    p = fmaf(p, f, 0.0555041f);
    p = fmaf(p, f, 0.2402265f);
    p = fmaf(p, f, 0.6931472f);
    p = fmaf(p, f, 1.0f);
    return __int_as_float(__float_as_int(p) + (n << 23));
}

// ---------------- flash attention fp16 (R8/R9 exact, proven) ----------------
#define FA_SMEM_BYTES 36864
__global__ void __launch_bounds__(256, 2) flash_kernel(
    const __half* __restrict__ qkv, __half* __restrict__ obuf) {
    extern __shared__ uint32_t sh[];
    int qt = blockIdx.x, bh = blockIdx.y;
    int b = bh >> 4, hd = bh & 15;
    const __half* Qg = qkv + (size_t)b * L_ * (3 * C_) + hd * 64;
    const __half* Kg = Qg + C_;
    const __half* Vg = Qg + 2 * C_;

    int tid = threadIdx.x;
    int w = tid >> 5, lane = tid & 31, g = lane >> 2, tq = lane & 3;
    int wm = w * 16;
    int grp = lane >> 3, rig = lane & 7;
    uint32_t sbase = (uint32_t)__cvta_generic_to_shared(sh);

    uint32_t qf[4][4];
    {
        const uint32_t* q0 = (const uint32_t*)(Qg + (size_t)(qt * 128 + wm + g) * (3 * C_));
        const uint32_t* q1 = (const uint32_t*)(Qg + (size_t)(qt * 128 + wm + g + 8) * (3 * C_));
#pragma unroll
        for (int s = 0; s < 4; s++) {
            qf[s][0] = q0[8 * s + tq];
            qf[s][1] = q1[8 * s + tq];
            qf[s][2] = q0[8 * s + tq + 4];
            qf[s][3] = q1[8 * s + tq + 4];
        }
    }

#define ISSUE_KV(kt, bf)                                                           \
    {                                                                              \
        _Pragma("unroll")                                                          \
        for (int i = 0; i < 2; i++) {                                              \
            int ci = tid + i * 256;                                                \
            int row = ci >> 3, q = ci & 7;                                         \
            cp16(sbase + ((bf) * 2304 + row * 36 + q * 4) * 4,                     \
                 Kg + (size_t)((kt) * 64 + row) * (3 * C_) + q * 8);               \
        }                                                                          \
        _Pragma("unroll")                                                          \
        for (int i = 0; i < 2; i++) {                                              \
            int ci = tid + i * 256;                                                \
            int row = ci >> 3, q = ci & 7;                                         \
            cp16(sbase + (4608 + (bf) * 2304 + row * 36 + q * 4) * 4,              \
                 Vg + (size_t)((kt) * 64 + row) * (3 * C_) + q * 8);               \
        }                                                                          \
    }

    ISSUE_KV(0, 0);
    CP_COMMIT();

    float l0 = 0.0f, l1 = 0.0f;
    float oacc[8][4];
#pragma unroll
    for (int nt = 0; nt < 8; nt++)
#pragma unroll
        for (int j = 0; j < 4; j++) oacc[nt][j] = 0.0f;

    for (int kt = 0; kt < L_ / 64; kt++) {
        int bf = kt & 1;
        CP_WAIT(0);
        __syncthreads();
        if (kt + 1 < L_ / 64) { ISSUE_KV(kt + 1, bf ^ 1); }
        CP_COMMIT();

        uint32_t Kb = sbase + (bf * 2304) * 4;
        uint32_t Vb = sbase + (4608 + bf * 2304) * 4;

        float sacc[8][4];
#pragma unroll
        for (int nt = 0; nt < 8; nt++)
#pragma unroll
            for (int j = 0; j < 4; j++) sacc[nt][j] = 0.0f;
#pragma unroll
        for (int s = 0; s < 4; s++) {
#pragma unroll
            for (int p = 0; p < 4; p++) {
                uint32_t b0, b1, b2, b3;
                uint32_t addr = Kb +
                    ((p * 16 + ((grp >> 1) << 3) + rig) * 36 + 8 * s + ((grp & 1) << 2)) * 4;
                ldsm4(b0, b1, b2, b3, addr);
                uint32_t bb0[2] = {b0, b1}, bb1[2] = {b2, b3};
                mma_f16(sacc[2 * p], qf[s], bb0);
                mma_f16(sacc[2 * p + 1], qf[s], bb1);
            }
        }

        uint32_t ph[8][2];
#pragma unroll
        for (int nt = 0; nt < 8; nt++) {
            float p0 = exp2s(sacc[nt][0]);
            float p1 = exp2s(sacc[nt][1]);
            float p2 = exp2s(sacc[nt][2]);
            float p3 = exp2s(sacc[nt][3]);
            l0 += p0 + p1;
            l1 += p2 + p3;
            ph[nt][0] = packh2(p0, p1);
            ph[nt][1] = packh2(p2, p3);
        }

#pragma unroll
        for (int s = 0; s < 4; s++) {
            uint32_t a[4] = {ph[2 * s][0], ph[2 * s][1], ph[2 * s + 1][0], ph[2 * s + 1][1]};
#pragma unroll
            for (int p = 0; p < 4; p++) {
                uint32_t b0, b1, b2, b3;
                uint32_t addr = Vb +
                    ((16 * s + ((grp & 1) << 3) + rig) * 36 + 8 * p + ((grp >> 1) << 2)) * 4;
                ldsm4t(b0, b1, b2, b3, addr);
                uint32_t bb0[2] = {b0, b1}, bb1[2] = {b2, b3};
                mma_f16(oacc[2 * p], a, bb0);
                mma_f16(oacc[2 * p + 1], a, bb1);
            }
        }
    }
#undef ISSUE_KV

    l0 += __shfl_xor_sync(0xffffffffu, l0, 1);
    l0 += __shfl_xor_sync(0xffffffffu, l0, 2);
    l1 += __shfl_xor_sync(0xffffffffu, l1, 1);
    l1 += __shfl_xor_sync(0xffffffffu, l1, 2);
    float inv0 = 1.0f / l0, inv1 = 1.0f / l1;
    size_t r0 = (size_t)(b * L_ + qt * 128 + wm + g) * C_ + hd * 64;
    size_t r1 = r0 + (size_t)8 * C_;
#pragma unroll
    for (int nt = 0; nt < 8; nt++) {
        ((uint32_t*)(obuf + r0))[nt * 4 + tq] = packh2(oacc[nt][0] * inv0, oacc[nt][1] * inv0);
        ((uint32_t*)(obuf + r1))[nt * 4 + tq] = packh2(oacc[nt][2] * inv1, oacc[nt][3] * inv1);
    }
}

// ---------------- dense fp16 GEMM (R9 proven): 128x128 CTA, 4 warps, 4 stages, 2 CTAs/SM ----------------
#define STG_W 5120
#define GE_SMEM_BYTES (4 * STG_W * 4)
// EPI: 1 = +bias (half out), 2 = gelu(+bias) (half out), 3 = xin + (acc+bias)*gate (f32 out)
template <int EPI>
__global__ void __launch_bounds__(128, 2) gemm_h(
    const __half* __restrict__ A, const __half* __restrict__ Bw,
    const float* __restrict__ bias, const float* __restrict__ xin,
    const float* __restrict__ gate, void* __restrict__ Cout,
    int N, int K) {
    extern __shared__ uint32_t sh[];
    int bm = blockIdx.y * 128, bn = blockIdx.x * 128;
    int tid = threadIdx.x;
    int w = tid >> 5, lane = tid & 31;
    int wm = (w & 1) * 64, wn = (w >> 1) * 64;
    int g = lane >> 2, tq = lane & 3;
    int grp = lane >> 3, rig = lane & 7;
    uint32_t sbase = (uint32_t)__cvta_generic_to_shared(sh);

#define GISSUE(s, kt)                                                              \
    {                                                                              \
        _Pragma("unroll")                                                          \
        for (int it = 0; it < 4; it++) {                                           \
            int ci = tid + it * 128;                                               \
            int row = ci >> 2, q = ci & 3;                                         \
            cp16(sbase + ((s) * STG_W + row * 20 + q * 4) * 4,                     \
                 A + (size_t)(bm + row) * K + (kt) * 32 + q * 8);                  \
        }                                                                          \
        _Pragma("unroll")                                                          \
        for (int it = 0; it < 4; it++) {                                           \
            int ci = tid + it * 128;                                               \
            int row = ci >> 2, q = ci & 3;                                         \
            cp16(sbase + ((s) * STG_W + 2560 + row * 20 + q * 4) * 4,              \
                 Bw + (size_t)(bn + row) * K + (kt) * 32 + q * 8);                 \
        }                                                                          \
    }

    int nk = K / 32;
    GISSUE(0, 0); CP_COMMIT();
    GISSUE(1, 1); CP_COMMIT();
    GISSUE(2, 2); CP_COMMIT();

    float acc[4][8][4];
#pragma unroll
    for (int i = 0; i < 4; i++)
#pragma unroll
        for (int j = 0; j < 8; j++)
#pragma unroll
            for (int k = 0; k < 4; k++) acc[i][j][k] = 0.0f;

    for (int kt = 0; kt < nk; kt++) {
        int rs = kt & 3;
        CP_WAIT(2);
        __syncthreads();
        if (kt + 3 < nk) { GISSUE((kt + 3) & 3, kt + 3); }
        CP_COMMIT();

        uint32_t stA = sbase + (rs * STG_W) * 4;
        uint32_t stB = stA + 2560 * 4;
#pragma unroll
        for (int s2 = 0; s2 < 2; s2++) {
            uint32_t af[4][4];
#pragma unroll
            for (int mt = 0; mt < 4; mt++) {
                uint32_t addr = stA +
                    ((wm + mt * 16 + ((grp & 1) << 3) + rig) * 20 +
                     8 * s2 + ((grp >> 1) << 2)) * 4;
                ldsm4(af[mt][0], af[mt][1], af[mt][2], af[mt][3], addr);
            }
            uint32_t bf[8][2];
#pragma unroll
            for (int nb = 0; nb < 4; nb++) {
                uint32_t b0, b1, b2, b3;
                uint32_t addr = stB +
                    ((wn + nb * 16 + ((grp >> 1) << 3) + rig) * 20 +
                     8 * s2 + ((grp & 1) << 2)) * 4;
                ldsm4(b0, b1, b2, b3, addr);
                bf[2 * nb][0] = b0; bf[2 * nb][1] = b1;
                bf[2 * nb + 1][0] = b2; bf[2 * nb + 1][1] = b3;
            }
#pragma unroll
            for (int mt = 0; mt < 4; mt++)
#pragma unroll
                for (int nt = 0; nt < 8; nt++)
                    mma_f16(acc[mt][nt], af[mt], bf[nt]);
        }
    }
#undef GISSUE

    // epilogue
#pragma unroll
    for (int mt = 0; mt < 4; mt++) {
#pragma unroll
        for (int i = 0; i < 2; i++) {
            int r = bm + wm + mt * 16 + g + i * 8;
            int bb = r >> 11;
#pragma unroll
            for (int nt = 0; nt < 8; nt++) {
                int c = bn + wn + nt * 8 + tq * 2;
                float v0 = acc[mt][nt][i * 2 + 0] + bias[c];
                float v1 = acc[mt][nt][i * 2 + 1] + bias[c + 1];
                if (EPI == 2) { v0 = gelu_f(v0); v1 = gelu_f(v1); }
                if (EPI == 3) {
                    float* Cf = (float*)Cout;
                    v0 = xin[(size_t)r * N + c]     + v0 * gate[bb * (6 * C_) + c];
                    v1 = xin[(size_t)r * N + c + 1] + v1 * gate[bb * (6 * C_) + c + 1];
                    Cf[(size_t)r * N + c]     = v0;
                    Cf[(size_t)r * N + c + 1] = v1;
                } else {
                    __half* Ch = (__half*)Cout;
                    ((uint32_t*)(Ch + (size_t)r * N))[c >> 1] = packh2(v0, v1);
                }
            }
        }
    }
}

// ---------------- launch ----------------
extern "C" void kernel_launch(void* const* d_in, const int* in_sizes, int n_in,
                              void* d_out, int out_size) {
    const float* feats  = (const float*)d_in[0];
    const float* mod    = (const float*)d_in[1];
    const float* w_mod  = (const float*)d_in[2];
    const float* b_mod  = (const float*)d_in[3];
    const float* w_qkv  = (const float*)d_in[4];
    const float* b_qkv  = (const float*)d_in[5];
    const float* w_proj = (const float*)d_in[6];
    const float* b_proj = (const float*)d_in[7];
    const float* w_fc1  = (const float*)d_in[8];
    const float* b_fc1  = (const float*)d_in[9];
    const float* w_fc2  = (const float*)d_in[10];
    const float* b_fc2  = (const float*)d_in[11];
    float* out = (float*)d_out;

    float* mod6; __half* h; __half* qkv; __half* obuf; float* xbuf; __half* gbuf;
    __half* wh;
    cudaGetSymbolAddress((void**)&mod6, g_mod6);
    cudaGetSymbolAddress((void**)&h,    g_h);
    cudaGetSymbolAddress((void**)&qkv,  g_qkv);
    cudaGetSymbolAddress((void**)&obuf, g_o);
    cudaGetSymbolAddress((void**)&xbuf, g_x);
    cudaGetSymbolAddress((void**)&gbuf, g_g);
    cudaGetSymbolAddress((void**)&wh,   g_wh);

    __half* wqkvh = wh;                         // [3072][1024]
    __half* wprojh = wqkvh + 3 * C_ * C_;       // [1024][1024]
    __half* wfc1h  = wprojh + C_ * C_;          // [4096][1024]
    __half* wfc2h  = wfc1h + 4 * C_ * C_;       // [1024][4096]

    cudaFuncSetAttribute(flash_kernel, cudaFuncAttributeMaxDynamicSharedMemorySize, FA_SMEM_BYTES);
    cudaFuncSetAttribute(gemm_h<1>, cudaFuncAttributeMaxDynamicSharedMemorySize, GE_SMEM_BYTES);
    cudaFuncSetAttribute(gemm_h<2>, cudaFuncAttributeMaxDynamicSharedMemorySize, GE_SMEM_BYTES);
    cudaFuncSetAttribute(gemm_h<3>, cudaFuncAttributeMaxDynamicSharedMemorySize, GE_SMEM_BYTES);

    // 0. weight transpose+convert to half [N][K]
    wconvT_kernel<<<dim3(C_ / 32, 3 * C_ / 32), dim3(32, 8)>>>(w_qkv, wqkvh, C_, 3 * C_);
    wconvT_kernel<<<dim3(C_ / 32, C_ / 32), dim3(32, 8)>>>(w_proj, wprojh, C_, C_);
    wconvT_kernel<<<dim3(C_ / 32, 4 * C_ / 32), dim3(32, 8)>>>(w_fc1, wfc1h, C_, 4 * C_);
    wconvT_kernel<<<dim3(4 * C_ / 32, C_ / 32), dim3(32, 8)>>>(w_fc2, wfc2h, 4 * C_, C_);

    // 1. adaLN modulation vector (split-K x4)
    mod_kernel<<<dim3(6 * C_ / 64, B_), 256>>>(mod, w_mod, b_mod, mod6);

    // 2. LN1 + (shift_a, scale_a) -> half (warp-per-row)
    ln_mod_kernel<<<M_ / 8, 256>>>(feats, h, mod6, 0, 1);

    // 3. qkv = h @ w_qkv + b_qkv -> half
    gemm_h<1><<<dim3(24, 32), 128, GE_SMEM_BYTES>>>(
        h, wqkvh, b_qkv, nullptr, nullptr, qkv, 3 * C_, C_);

    // 4. fused flash attention -> obuf (half)
    flash_kernel<<<dim3(16, 32), 256, FA_SMEM_BYTES>>>(qkv, obuf);

    // 5. x = feats + (O @ w_proj + b_proj) * gate_a -> f32
    gemm_h<3><<<dim3(8, 32), 128, GE_SMEM_BYTES>>>(
        obuf, wprojh, b_proj, feats, mod6 + 2 * C_, xbuf, C_, C_);

    // 6. LN2 + (shift_m, scale_m) -> half (warp-per-row)
    ln_mod_kernel<<<M_ / 8, 256>>>(xbuf, h, mod6, 3, 4);

    // 7. g = gelu(h @ w_fc1 + b_fc1) -> half
    gemm_h<2><<<dim3(32, 32), 128, GE_SMEM_BYTES>>>(
        h, wfc1h, b_fc1, nullptr, nullptr, gbuf, 4 * C_, C_);

    // 8. out = x + (g @ w_fc2 + b_fc2) * gate_m -> f32
    gemm_h<3><<<dim3(8, 32), 128, GE_SMEM_BYTES>>>(
        gbuf, wfc2h, b_fc2, xbuf, mod6 + 5 * C_, out, C_, 4 * C_);
}

// round 17
// speedup vs baseline: 1.2458x; 1.0329x over previous
#include <cuda_runtime.h>
#include <cuda_fp16.h>
#include <math.h>
#include <stdint.h>

#define B_ 2
#define L_ 2048
#define C_ 1024
#define H_ 16
#define M_ 4096   // B_*L_

// ---------------- scratch (static device globals; no allocation) ----------------
__device__ float    g_mod6[B_ * 6 * C_];
__device__ __half   g_h[M_ * C_];
__device__ __half   g_qkv[M_ * 3 * C_];
__device__ __half   g_o[M_ * C_];
__device__ float    g_x[M_ * C_];
__device__ __half   g_g[M_ * 4 * C_];
__device__ __half   g_wh[12 * C_ * C_];

// ---------------- cp.async helpers ----------------
__device__ __forceinline__ void cp16(uint32_t dst, const void* src) {
    asm volatile("cp.async.cg.shared.global [%0], [%1], 16;\n" :: "r"(dst), "l"(src));
}
#define CP_COMMIT() asm volatile("cp.async.commit_group;\n" ::: "memory")
#define CP_WAIT(n)  asm volatile("cp.async.wait_group %0;\n" :: "n"(n) : "memory")

// ---------------- mma / ldmatrix helpers ----------------
__device__ __forceinline__ void mma_f16(float* d, const uint32_t* a, const uint32_t* b) {
    asm volatile(
        "mma.sync.aligned.m16n8k16.row.col.f32.f16.f16.f32 "
        "{%0,%1,%2,%3}, {%4,%5,%6,%7}, {%8,%9}, {%0,%1,%2,%3};\n"
        : "+f"(d[0]), "+f"(d[1]), "+f"(d[2]), "+f"(d[3])
        : "r"(a[0]), "r"(a[1]), "r"(a[2]), "r"(a[3]), "r"(b[0]), "r"(b[1]));
}
__device__ __forceinline__ void ldsm4(uint32_t& r0, uint32_t& r1, uint32_t& r2, uint32_t& r3,
                                      uint32_t addr) {
    asm volatile("ldmatrix.sync.aligned.m8n8.x4.shared.b16 {%0,%1,%2,%3}, [%4];"
                 : "=r"(r0), "=r"(r1), "=r"(r2), "=r"(r3) : "r"(addr));
}
__device__ __forceinline__ void ldsm4t(uint32_t& r0, uint32_t& r1, uint32_t& r2, uint32_t& r3,
                                       uint32_t addr) {
    asm volatile("ldmatrix.sync.aligned.m8n8.x4.trans.shared.b16 {%0,%1,%2,%3}, [%4];"
                 : "=r"(r0), "=r"(r1), "=r"(r2), "=r"(r3) : "r"(addr));
}
__device__ __forceinline__ uint32_t packh2(float a, float b) {
    __half2 h = __floats2half2_rn(a, b);
    uint32_t u;
    *(__half2*)&u = h;
    return u;
}

// ---------------- weight transpose+convert v2: f32 [K][N] -> half [N][K], half2 stores ----------------
// 64k x 32n tiles, threads (32,8). Reads 128B-coalesced, writes 128B-coalesced uint32.
__global__ void wconvT_kernel(const float* __restrict__ w, __half* __restrict__ o,
                              int K, int N) {
    __shared__ float t[64][33];
    int bx = blockIdx.x * 64;   // k base
    int by = blockIdx.y * 32;   // n base
    int x = threadIdx.x, y = threadIdx.y;
#pragma unroll
    for (int j = 0; j < 64; j += 8)
        t[y + j][x] = w[(size_t)(bx + y + j) * N + by + x];
    __syncthreads();
#pragma unroll
    for (int j = 0; j < 32; j += 8) {
        int n = by + y + j;
        uint32_t pk = packh2(t[2 * x][y + j], t[2 * x + 1][y + j]);
        *(uint32_t*)(o + (size_t)n * K + bx + 2 * x) = pk;
    }
}

// ---------------- adaLN modulation v3: split-K x8, 32 outputs/block ----------------
// grid (6C/32, B_), 256 threads. thread: n = t&31, kc = t>>5 (0..7, 128 k each)
__global__ void __launch_bounds__(256) mod_kernel(
    const float* __restrict__ mod, const float* __restrict__ w,
    const float* __restrict__ b, float* __restrict__ out) {
    __shared__ float sm[C_];
    __shared__ float part[8][32];
    int batch = blockIdx.y;
    const float* mrow = mod + batch * C_;
    for (int i = threadIdx.x; i < C_; i += 256) {
        float v = mrow[i];
        sm[i] = v / (1.0f + expf(-v));
    }
    __syncthreads();
    int t = threadIdx.x;
    int nl = t & 31, kc = t >> 5;
    int n = blockIdx.x * 32 + nl;
    const float* wp = w + (size_t)(kc * 128) * (6 * C_) + n;
    float acc = 0.0f;
#pragma unroll 4
    for (int k = 0; k < 128; k++)
        acc += sm[kc * 128 + k] * wp[(size_t)k * (6 * C_)];
    part[kc][nl] = acc;
    __syncthreads();
    if (kc == 0) {
        float tot = part[0][nl] + part[1][nl] + part[2][nl] + part[3][nl]
                  + part[4][nl] + part[5][nl] + part[6][nl] + part[7][nl] + b[n];
        out[batch * (6 * C_) + n] = tot;
    }
}

// ---------------- LayerNorm + modulation: one warp per row (R15 proven) ----------------
__global__ void __launch_bounds__(256) ln_mod_kernel(
    const float* __restrict__ x, __half* __restrict__ out,
    const float* __restrict__ mod6, int shiftChunk, int scaleChunk) {
    int wid = threadIdx.x >> 5, lane = threadIdx.x & 31;
    int r = blockIdx.x * 8 + wid;
    int b = r >> 11;
    const float4* row4 = (const float4*)(x + (size_t)r * C_);

    float4 v[8];
    float s = 0.0f;
#pragma unroll
    for (int i = 0; i < 8; i++) {
        v[i] = row4[i * 32 + lane];
        s += v[i].x + v[i].y + v[i].z + v[i].w;
    }
#pragma unroll
    for (int o = 16; o > 0; o >>= 1) s += __shfl_xor_sync(0xffffffffu, s, o);
    float mean = s * (1.0f / C_);

    float q = 0.0f;
#pragma unroll
    for (int i = 0; i < 8; i++) {
        float dx = v[i].x - mean, dy = v[i].y - mean;
        float dz = v[i].z - mean, dw = v[i].w - mean;
        q += dx * dx + dy * dy + dz * dz + dw * dw;
    }
#pragma unroll
    for (int o = 16; o > 0; o >>= 1) q += __shfl_xor_sync(0xffffffffu, q, o);
    float rstd = rsqrtf(q * (1.0f / C_) + 1e-6f);

    const float4* sc4 = (const float4*)(mod6 + b * (6 * C_) + scaleChunk * C_);
    const float4* sf4 = (const float4*)(mod6 + b * (6 * C_) + shiftChunk * C_);
    uint2* o2 = (uint2*)(out + (size_t)r * C_);
#pragma unroll
    for (int i = 0; i < 8; i++) {
        float4 sc = sc4[i * 32 + lane];
        float4 sf = sf4[i * 32 + lane];
        float n0 = (v[i].x - mean) * rstd * (1.0f + sc.x) + sf.x;
        float n1 = (v[i].y - mean) * rstd * (1.0f + sc.y) + sf.y;
        float n2 = (v[i].z - mean) * rstd * (1.0f + sc.z) + sf.z;
        float n3 = (v[i].w - mean) * rstd * (1.0f + sc.w) + sf.w;
        uint2 pk;
        pk.x = packh2(n0, n1);
        pk.y = packh2(n2, n3);
        o2[i * 32 + lane] = pk;
    }
}

// ---------------- misc ----------------
__device__ __forceinline__ float gelu_f(float x) {
    return 0.5f * x * (1.0f + erff(x * 0.70710678118654752f));
}

__device__ __forceinline__ float exp2s(float s) {
    const float SC = 0.125f * 1.4426950408889634f;
    float tr = fmaf(s, SC, 12582912.0f);
    int n = __float_as_int(tr) - 0x4B400000;
    float f = fmaf(s, SC, 12582912.0f - tr);
    float p = 0.0096181f;
    p = fmaf(p, f, 0.0555041f);
    p = fmaf(p, f, 0.2402265f);
    p = fmaf(p, f, 0.6931472f);
    p = fmaf(p, f, 1.0f);
    return __int_as_float(__float_as_int(p) + (n << 23));
}

// ---------------- flash attention fp16 (R8/R9 exact, proven) ----------------
#define FA_SMEM_BYTES 36864
__global__ void __launch_bounds__(256, 2) flash_kernel(
    const __half* __restrict__ qkv, __half* __restrict__ obuf) {
    extern __shared__ uint32_t sh[];
    int qt = blockIdx.x, bh = blockIdx.y;
    int b = bh >> 4, hd = bh & 15;
    const __half* Qg = qkv + (size_t)b * L_ * (3 * C_) + hd * 64;
    const __half* Kg = Qg + C_;
    const __half* Vg = Qg + 2 * C_;

    int tid = threadIdx.x;
    int w = tid >> 5, lane = tid & 31, g = lane >> 2, tq = lane & 3;
    int wm = w * 16;
    int grp = lane >> 3, rig = lane & 7;
    uint32_t sbase = (uint32_t)__cvta_generic_to_shared(sh);

    uint32_t qf[4][4];
    {
        const uint32_t* q0 = (const uint32_t*)(Qg + (size_t)(qt * 128 + wm + g) * (3 * C_));
        const uint32_t* q1 = (const uint32_t*)(Qg + (size_t)(qt * 128 + wm + g + 8) * (3 * C_));
#pragma unroll
        for (int s = 0; s < 4; s++) {
            qf[s][0] = q0[8 * s + tq];
            qf[s][1] = q1[8 * s + tq];
            qf[s][2] = q0[8 * s + tq + 4];
            qf[s][3] = q1[8 * s + tq + 4];
        }
    }

#define ISSUE_KV(kt, bf)                                                           \
    {                                                                              \
        _Pragma("unroll")                                                          \
        for (int i = 0; i < 2; i++) {                                              \
            int ci = tid + i * 256;                                                \
            int row = ci >> 3, q = ci & 7;                                         \
            cp16(sbase + ((bf) * 2304 + row * 36 + q * 4) * 4,                     \
                 Kg + (size_t)((kt) * 64 + row) * (3 * C_) + q * 8);               \
        }                                                                          \
        _Pragma("unroll")                                                          \
        for (int i = 0; i < 2; i++) {                                              \
            int ci = tid + i * 256;                                                \
            int row = ci >> 3, q = ci & 7;                                         \
            cp16(sbase + (4608 + (bf) * 2304 + row * 36 + q * 4) * 4,              \
                 Vg + (size_t)((kt) * 64 + row) * (3 * C_) + q * 8);               \
        }                                                                          \
    }

    ISSUE_KV(0, 0);
    CP_COMMIT();

    float l0 = 0.0f, l1 = 0.0f;
    float oacc[8][4];
#pragma unroll
    for (int nt = 0; nt < 8; nt++)
#pragma unroll
        for (int j = 0; j < 4; j++) oacc[nt][j] = 0.0f;

    for (int kt = 0; kt < L_ / 64; kt++) {
        int bf = kt & 1;
        CP_WAIT(0);
        __syncthreads();
        if (kt + 1 < L_ / 64) { ISSUE_KV(kt + 1, bf ^ 1); }
        CP_COMMIT();

        uint32_t Kb = sbase + (bf * 2304) * 4;
        uint32_t Vb = sbase + (4608 + bf * 2304) * 4;

        float sacc[8][4];
#pragma unroll
        for (int nt = 0; nt < 8; nt++)
#pragma unroll
            for (int j = 0; j < 4; j++) sacc[nt][j] = 0.0f;
#pragma unroll
        for (int s = 0; s < 4; s++) {
#pragma unroll
            for (int p = 0; p < 4; p++) {
                uint32_t b0, b1, b2, b3;
                uint32_t addr = Kb +
                    ((p * 16 + ((grp >> 1) << 3) + rig) * 36 + 8 * s + ((grp & 1) << 2)) * 4;
                ldsm4(b0, b1, b2, b3, addr);
                uint32_t bb0[2] = {b0, b1}, bb1[2] = {b2, b3};
                mma_f16(sacc[2 * p], qf[s], bb0);
                mma_f16(sacc[2 * p + 1], qf[s], bb1);
            }
        }

        uint32_t ph[8][2];
#pragma unroll
        for (int nt = 0; nt < 8; nt++) {
            float p0 = exp2s(sacc[nt][0]);
            float p1 = exp2s(sacc[nt][1]);
            float p2 = exp2s(sacc[nt][2]);
            float p3 = exp2s(sacc[nt][3]);
            l0 += p0 + p1;
            l1 += p2 + p3;
            ph[nt][0] = packh2(p0, p1);
            ph[nt][1] = packh2(p2, p3);
        }

#pragma unroll
        for (int s = 0; s < 4; s++) {
            uint32_t a[4] = {ph[2 * s][0], ph[2 * s][1], ph[2 * s + 1][0], ph[2 * s + 1][1]};
#pragma unroll
            for (int p = 0; p < 4; p++) {
                uint32_t b0, b1, b2, b3;
                uint32_t addr = Vb +
                    ((16 * s + ((grp & 1) << 3) + rig) * 36 + 8 * p + ((grp >> 1) << 2)) * 4;
                ldsm4t(b0, b1, b2, b3, addr);
                uint32_t bb0[2] = {b0, b1}, bb1[2] = {b2, b3};
                mma_f16(oacc[2 * p], a, bb0);
                mma_f16(oacc[2 * p + 1], a, bb1);
            }
        }
    }
#undef ISSUE_KV

    l0 += __shfl_xor_sync(0xffffffffu, l0, 1);
    l0 += __shfl_xor_sync(0xffffffffu, l0, 2);
    l1 += __shfl_xor_sync(0xffffffffu, l1, 1);
    l1 += __shfl_xor_sync(0xffffffffu, l1, 2);
    float inv0 = 1.0f / l0, inv1 = 1.0f / l1;
    size_t r0 = (size_t)(b * L_ + qt * 128 + wm + g) * C_ + hd * 64;
    size_t r1 = r0 + (size_t)8 * C_;
#pragma unroll
    for (int nt = 0; nt < 8; nt++) {
        ((uint32_t*)(obuf + r0))[nt * 4 + tq] = packh2(oacc[nt][0] * inv0, oacc[nt][1] * inv0);
        ((uint32_t*)(obuf + r1))[nt * 4 + tq] = packh2(oacc[nt][2] * inv1, oacc[nt][3] * inv1);
    }
}

// ---------------- dense fp16 GEMM (R9 proven): 128x128 CTA, 4 warps, 4 stages, 2 CTAs/SM ----------------
#define STG_W 5120
#define GE_SMEM_BYTES (4 * STG_W * 4)
// EPI: 1 = +bias (half out), 2 = gelu(+bias) (half out), 3 = xin + (acc+bias)*gate (f32 out)
template <int EPI>
__global__ void __launch_bounds__(128, 2) gemm_h(
    const __half* __restrict__ A, const __half* __restrict__ Bw,
    const float* __restrict__ bias, const float* __restrict__ xin,
    const float* __restrict__ gate, void* __restrict__ Cout,
    int N, int K) {
    extern __shared__ uint32_t sh[];
    int bm = blockIdx.y * 128, bn = blockIdx.x * 128;
    int tid = threadIdx.x;
    int w = tid >> 5, lane = tid & 31;
    int wm = (w & 1) * 64, wn = (w >> 1) * 64;
    int g = lane >> 2, tq = lane & 3;
    int grp = lane >> 3, rig = lane & 7;
    uint32_t sbase = (uint32_t)__cvta_generic_to_shared(sh);

#define GISSUE(s, kt)                                                              \
    {                                                                              \
        _Pragma("unroll")                                                          \
        for (int it = 0; it < 4; it++) {                                           \
            int ci = tid + it * 128;                                               \
            int row = ci >> 2, q = ci & 3;                                         \
            cp16(sbase + ((s) * STG_W + row * 20 + q * 4) * 4,                     \
                 A + (size_t)(bm + row) * K + (kt) * 32 + q * 8);                  \
        }                                                                          \
        _Pragma("unroll")                                                          \
        for (int it = 0; it < 4; it++) {                                           \
            int ci = tid + it * 128;                                               \
            int row = ci >> 2, q = ci & 3;                                         \
            cp16(sbase + ((s) * STG_W + 2560 + row * 20 + q * 4) * 4,              \
                 Bw + (size_t)(bn + row) * K + (kt) * 32 + q * 8);                 \
        }                                                                          \
    }

    int nk = K / 32;
    GISSUE(0, 0); CP_COMMIT();
    GISSUE(1, 1); CP_COMMIT();
    GISSUE(2, 2); CP_COMMIT();

    float acc[4][8][4];
#pragma unroll
    for (int i = 0; i < 4; i++)
#pragma unroll
        for (int j = 0; j < 8; j++)
#pragma unroll
            for (int k = 0; k < 4; k++) acc[i][j][k] = 0.0f;

    for (int kt = 0; kt < nk; kt++) {
        int rs = kt & 3;
        CP_WAIT(2);
        __syncthreads();
        if (kt + 3 < nk) { GISSUE((kt + 3) & 3, kt + 3); }
        CP_COMMIT();

        uint32_t stA = sbase + (rs * STG_W) * 4;
        uint32_t stB = stA + 2560 * 4;
#pragma unroll
        for (int s2 = 0; s2 < 2; s2++) {
            uint32_t af[4][4];
#pragma unroll
            for (int mt = 0; mt < 4; mt++) {
                uint32_t addr = stA +
                    ((wm + mt * 16 + ((grp & 1) << 3) + rig) * 20 +
                     8 * s2 + ((grp >> 1) << 2)) * 4;
                ldsm4(af[mt][0], af[mt][1], af[mt][2], af[mt][3], addr);
            }
            uint32_t bf[8][2];
#pragma unroll
            for (int nb = 0; nb < 4; nb++) {
                uint32_t b0, b1, b2, b3;
                uint32_t addr = stB +
                    ((wn + nb * 16 + ((grp >> 1) << 3) + rig) * 20 +
                     8 * s2 + ((grp & 1) << 2)) * 4;
                ldsm4(b0, b1, b2, b3, addr);
                bf[2 * nb][0] = b0; bf[2 * nb][1] = b1;
                bf[2 * nb + 1][0] = b2; bf[2 * nb + 1][1] = b3;
            }
#pragma unroll
            for (int mt = 0; mt < 4; mt++)
#pragma unroll
                for (int nt = 0; nt < 8; nt++)
                    mma_f16(acc[mt][nt], af[mt], bf[nt]);
        }
    }
#undef GISSUE

    // epilogue
#pragma unroll
    for (int mt = 0; mt < 4; mt++) {
#pragma unroll
        for (int i = 0; i < 2; i++) {
            int r = bm + wm + mt * 16 + g + i * 8;
            int bb = r >> 11;
#pragma unroll
            for (int nt = 0; nt < 8; nt++) {
                int c = bn + wn + nt * 8 + tq * 2;
                float v0 = acc[mt][nt][i * 2 + 0] + bias[c];
                float v1 = acc[mt][nt][i * 2 + 1] + bias[c + 1];
                if (EPI == 2) { v0 = gelu_f(v0); v1 = gelu_f(v1); }
                if (EPI == 3) {
                    float* Cf = (float*)Cout;
                    v0 = xin[(size_t)r * N + c]     + v0 * gate[bb * (6 * C_) + c];
                    v1 = xin[(size_t)r * N + c + 1] + v1 * gate[bb * (6 * C_) + c + 1];
                    Cf[(size_t)r * N + c]     = v0;
                    Cf[(size_t)r * N + c + 1] = v1;
                } else {
                    __half* Ch = (__half*)Cout;
                    ((uint32_t*)(Ch + (size_t)r * N))[c >> 1] = packh2(v0, v1);
                }
            }
        }
    }
}

// ---------------- launch ----------------
extern "C" void kernel_launch(void* const* d_in, const int* in_sizes, int n_in,
                              void* d_out, int out_size) {
    const float* feats  = (const float*)d_in[0];
    const float* mod    = (const float*)d_in[1];
    const float* w_mod  = (const float*)d_in[2];
    const float* b_mod  = (const float*)d_in[3];
    const float* w_qkv  = (const float*)d_in[4];
    const float* b_qkv  = (const float*)d_in[5];
    const float* w_proj = (const float*)d_in[6];
    const float* b_proj = (const float*)d_in[7];
    const float* w_fc1  = (const float*)d_in[8];
    const float* b_fc1  = (const float*)d_in[9];
    const float* w_fc2  = (const float*)d_in[10];
    const float* b_fc2  = (const float*)d_in[11];
    float* out = (float*)d_out;

    float* mod6; __half* h; __half* qkv; __half* obuf; float* xbuf; __half* gbuf;
    __half* wh;
    cudaGetSymbolAddress((void**)&mod6, g_mod6);
    cudaGetSymbolAddress((void**)&h,    g_h);
    cudaGetSymbolAddress((void**)&qkv,  g_qkv);
    cudaGetSymbolAddress((void**)&obuf, g_o);
    cudaGetSymbolAddress((void**)&xbuf, g_x);
    cudaGetSymbolAddress((void**)&gbuf, g_g);
    cudaGetSymbolAddress((void**)&wh,   g_wh);

    __half* wqkvh = wh;                         // [3072][1024]
    __half* wprojh = wqkvh + 3 * C_ * C_;       // [1024][1024]
    __half* wfc1h  = wprojh + C_ * C_;          // [4096][1024]
    __half* wfc2h  = wfc1h + 4 * C_ * C_;       // [1024][4096]

    cudaFuncSetAttribute(flash_kernel, cudaFuncAttributeMaxDynamicSharedMemorySize, FA_SMEM_BYTES);
    cudaFuncSetAttribute(gemm_h<1>, cudaFuncAttributeMaxDynamicSharedMemorySize, GE_SMEM_BYTES);
    cudaFuncSetAttribute(gemm_h<2>, cudaFuncAttributeMaxDynamicSharedMemorySize, GE_SMEM_BYTES);
    cudaFuncSetAttribute(gemm_h<3>, cudaFuncAttributeMaxDynamicSharedMemorySize, GE_SMEM_BYTES);

    // 0. weight transpose+convert to half [N][K] (64k x 32n tiles, half2 stores)
    wconvT_kernel<<<dim3(C_ / 64, 3 * C_ / 32), dim3(32, 8)>>>(w_qkv, wqkvh, C_, 3 * C_);
    wconvT_kernel<<<dim3(C_ / 64, C_ / 32), dim3(32, 8)>>>(w_proj, wprojh, C_, C_);
    wconvT_kernel<<<dim3(C_ / 64, 4 * C_ / 32), dim3(32, 8)>>>(w_fc1, wfc1h, C_, 4 * C_);
    wconvT_kernel<<<dim3(4 * C_ / 64, C_ / 32), dim3(32, 8)>>>(w_fc2, wfc2h, 4 * C_, C_);

    // 1. adaLN modulation vector (split-K x8)
    mod_kernel<<<dim3(6 * C_ / 32, B_), 256>>>(mod, w_mod, b_mod, mod6);

    // 2. LN1 + (shift_a, scale_a) -> half (warp-per-row)
    ln_mod_kernel<<<M_ / 8, 256>>>(feats, h, mod6, 0, 1);

    // 3. qkv = h @ w_qkv + b_qkv -> half
    gemm_h<1><<<dim3(24, 32), 128, GE_SMEM_BYTES>>>(
        h, wqkvh, b_qkv, nullptr, nullptr, qkv, 3 * C_, C_);

    // 4. fused flash attention -> obuf (half)
    flash_kernel<<<dim3(16, 32), 256, FA_SMEM_BYTES>>>(qkv, obuf);

    // 5. x = feats + (O @ w_proj + b_proj) * gate_a -> f32
    gemm_h<3><<<dim3(8, 32), 128, GE_SMEM_BYTES>>>(
        obuf, wprojh, b_proj, feats, mod6 + 2 * C_, xbuf, C_, C_);

    // 6. LN2 + (shift_m, scale_m) -> half (warp-per-row)
    ln_mod_kernel<<<M_ / 8, 256>>>(xbuf, h, mod6, 3, 4);

    // 7. g = gelu(h @ w_fc1 + b_fc1) -> half
    gemm_h<2><<<dim3(32, 32), 128, GE_SMEM_BYTES>>>(
        h, wfc1h, b_fc1, nullptr, nullptr, gbuf, 4 * C_, C_);

    // 8. out = x + (g @ w_fc2 + b_fc2) * gate_m -> f32
    gemm_h<3><<<dim3(8, 32), 128, GE_SMEM_BYTES>>>(
        gbuf, wfc2h, b_fc2, xbuf, mod6 + 5 * C_, out, C_, 4 * C_);
}